// round 13
// baseline (speedup 1.0000x reference)
#include <cuda_runtime.h>
#include <cuda_fp16.h>
#include <cstdint>

// Problem constants
#define Bn 8
#define Qn 900
#define EMBED 256
#define HEADS 8
#define LEVELS 4
#define POINTS 4
#define HEAD_DIM 32
#define NUM_KEYS 13294
#define BQ (Bn*Qn)            // 7200
#define MV (Bn*NUM_KEYS)      // 106352

#define NVB   ((MV + 127) / 128)      // 831 value CTAs (BM=128, BN=256)
#define NQB_Y ((BQ + 127) / 128)      // 57 query row-tiles
#define NQB   (NQB_Y * 3)             // 171 qproj CTAs

// Transposed fp16 weight regions within g_wt (units: halfs)
#define WT_VAL  0
#define WT_OFF  65536
#define WT_ATTN 131072
#define WT_OUT  163840

// Scratch (device globals; no runtime allocation)
__device__ __half g_vh [(size_t)MV * EMBED];  // projected value, fp16
__device__ float  g_qp [(size_t)BQ * 384];    // [off(256) | attn(128)] per query
__device__ float  g_tmp[(size_t)BQ * 256];
__device__ __half g_wt [229376];              // all weights, [n][k] fp16

__device__ __forceinline__ uint32_t packh2(float a, float b) {
    __half2 h = __floats2half2_rn(a, b);
    return *reinterpret_cast<uint32_t*>(&h);
}
__device__ __forceinline__ uint32_t smem_u32(const void* p) {
    uint32_t a;
    asm("{ .reg .u64 t; cvta.to.shared.u64 t, %1; cvt.u32.u64 %0, t; }"
        : "=r"(a) : "l"(p));
    return a;
}
__device__ __forceinline__ void ldsm_x4(uint32_t& r0, uint32_t& r1,
                                        uint32_t& r2, uint32_t& r3, uint32_t addr) {
    asm volatile("ldmatrix.sync.aligned.m8n8.x4.shared.b16 {%0,%1,%2,%3}, [%4];"
                 : "=r"(r0), "=r"(r1), "=r"(r2), "=r"(r3) : "r"(addr));
}
__device__ __forceinline__ void cp_async16(uint32_t dst, const void* src) {
    asm volatile("cp.async.cg.shared.global [%0], [%1], 16;"
                 :: "r"(dst), "l"(src) : "memory");
}
#define CP_COMMIT() asm volatile("cp.async.commit_group;" ::: "memory")
#define CP_WAIT0()  asm volatile("cp.async.wait_group 0;" ::: "memory")

// ---------------------------------------------------------------------------
// Weight transpose+convert: W[k][n] f32 -> Wt[n][k] f16 (rounding == packh2).
// ---------------------------------------------------------------------------
__global__ void transpose_w(const float* __restrict__ W_val,
                            const float* __restrict__ W_off,
                            const float* __restrict__ W_attn,
                            const float* __restrict__ W_out,
                            __half* __restrict__ Wt)
{
    const float* W; int N; int base;
    switch (blockIdx.z) {
        case 0:  W = W_val;  N = 256; base = WT_VAL;  break;
        case 1:  W = W_off;  N = 256; base = WT_OFF;  break;
        case 2:  W = W_attn; N = 128; base = WT_ATTN; break;
        default: W = W_out;  N = 256; base = WT_OUT;  break;
    }
    const int n0 = blockIdx.x * 32, k0 = blockIdx.y * 32;
    if (n0 >= N) return;

    __shared__ float t[32][33];
    const int tx = threadIdx.x, ty = threadIdx.y;
    #pragma unroll
    for (int i = 0; i < 4; i++)
        t[tx][ty + 8 * i] = W[(size_t)(k0 + ty + 8 * i) * N + n0 + tx];
    __syncthreads();
    const int id = ty * 32 + tx;
    #pragma unroll
    for (int i = 0; i < 2; i++) {
        int e = id + i * 256, n = e >> 4, kk = e & 15;
        uint32_t h = packh2(t[n][2 * kk], t[n][2 * kk + 1]);
        *reinterpret_cast<uint32_t*>(Wt + base + (size_t)(n0 + n) * 256 + k0 + 2 * kk) = h;
    }
}

// ---------------------------------------------------------------------------
// Shared GEMM core: NT threads, warp grid (NT/32/NWC rows x NWC cols),
// warp tile (MI*16) x 32, CTA tile BM x BN, K=256.
// A: fp32 gmem -> regs -> cvt -> smem [m][k2] stride 20 -> ldmatrix.x4.
// B: fp16 [n][k] gmem -> cp.async -> smem [n][k2] stride 20 -> ldmatrix.x4.
// Double-buffered, 1 sync/K-tile. (Fragment mapping validated rounds 8-12.)
// ---------------------------------------------------------------------------
template <int NT, int MI, int NWC, int BN, bool HOUT>
__device__ __forceinline__ void gemm_tile(
    const float* __restrict__ A, int M, int brow,
    const __half* __restrict__ Bt,     // weight rows [n][256], tile base applied
    const float* __restrict__ biasb,   // bias + bcol
    void* __restrict__ Cb,             // C base (tile col applied)
    int ldc,
    uint32_t* sm)
{
    constexpr int WROWS = NT / 32 / NWC;
    constexpr int BM    = MI * 16 * WROWS;
    constexpr int AST   = 20;
    constexpr int ASZW  = BM * AST;
    constexpr int ASZB  = ASZW * 4;
    constexpr int BSZW  = BN * AST;
    constexpr int STGW  = ASZW + BSZW;
    constexpr int STGB  = STGW * 4;
    constexpr int AIT   = BM * 8 / NT;   // A float4 loads per thread
    constexpr int BIT   = BN * 4 / NT;   // B cp.async per thread

    const int tid  = threadIdx.x;
    const int lane = tid & 31;
    const int w    = tid >> 5;
    const int gid  = lane >> 2;
    const int tig  = lane & 3;
    const int m0   = (w / NWC) * (MI * 16);
    const int n0   = (w % NWC) * 32;

    const uint32_t smbase = smem_u32(sm);
    const uint32_t aAddr = smbase + (uint32_t)(m0 + (lane & 15)) * 80
                                  + ((lane & 16) ? 16u : 0u);
    const uint32_t bAddr = smbase + ASZB
                                  + (uint32_t)(n0 + (lane & 7) + ((lane & 16) ? 8 : 0)) * 80
                                  + ((lane & 8) ? 16u : 0u);

    float acc[MI][4][4];
    #pragma unroll
    for (int mi = 0; mi < MI; mi++)
        #pragma unroll
        for (int nj = 0; nj < 4; nj++)
            #pragma unroll
            for (int r = 0; r < 4; r++) acc[mi][nj][r] = 0.f;

    float4 pa[AIT];

    auto issueB = [&](int t, int p) {
        const int k0 = t * 32;
        #pragma unroll
        for (int i = 0; i < BIT; ++i) {
            int g = tid + i * NT, n = g >> 2, ch = g & 3;
            uint32_t dst = smbase + (uint32_t)p * STGB + ASZB + (uint32_t)n * 80 + ch * 16;
            cp_async16(dst, Bt + (size_t)n * 256 + k0 + ch * 8);
        }
        CP_COMMIT();
    };
    auto loadA = [&](int k0) {
        #pragma unroll
        for (int i = 0; i < AIT; ++i) {
            int c = tid + i * NT, row = c >> 3, slot = c & 7;
            int gr = min(brow + row, M - 1);
            pa[i] = *reinterpret_cast<const float4*>(A + (size_t)gr * 256 + k0 + slot * 4);
        }
    };
    auto storeA = [&](int p) {
        uint32_t* As = sm + p * STGW;
        #pragma unroll
        for (int i = 0; i < AIT; ++i) {
            int c = tid + i * NT, row = c >> 3, slot = c & 7;
            uint2 t = { packh2(pa[i].x, pa[i].y), packh2(pa[i].z, pa[i].w) };
            *reinterpret_cast<uint2*>(&As[row * AST + 2 * slot]) = t;
        }
    };
    auto compute = [&](int p) {
        const uint32_t pb = (uint32_t)p * STGB;
        #pragma unroll
        for (int ks = 0; ks < 2; ks++) {
            uint32_t a[MI][4], b[4][2];
            #pragma unroll
            for (int mi = 0; mi < MI; mi++)
                ldsm_x4(a[mi][0], a[mi][1], a[mi][2], a[mi][3],
                        aAddr + pb + mi * 1280 + ks * 32);
            #pragma unroll
            for (int njp = 0; njp < 2; njp++)
                ldsm_x4(b[2 * njp][0], b[2 * njp][1], b[2 * njp + 1][0], b[2 * njp + 1][1],
                        bAddr + pb + njp * 1280 + ks * 32);
            #pragma unroll
            for (int mi = 0; mi < MI; mi++)
                #pragma unroll
                for (int nj = 0; nj < 4; nj++) {
                    asm volatile(
                        "mma.sync.aligned.m16n8k16.row.col.f32.f16.f16.f32 "
                        "{%0,%1,%2,%3}, {%4,%5,%6,%7}, {%8,%9}, {%0,%1,%2,%3};"
                        : "+f"(acc[mi][nj][0]), "+f"(acc[mi][nj][1]),
                          "+f"(acc[mi][nj][2]), "+f"(acc[mi][nj][3])
                        : "r"(a[mi][0]), "r"(a[mi][1]), "r"(a[mi][2]), "r"(a[mi][3]),
                          "r"(b[nj][0]), "r"(b[nj][1]));
                }
        }
    };

    issueB(0, 0);
    loadA(0);
    storeA(0);
    CP_WAIT0();
    __syncthreads();
    #pragma unroll 1
    for (int t = 0; t < 8; t++) {
        if (t < 7) { issueB(t + 1, (t + 1) & 1); loadA((t + 1) * 32); }
        compute(t & 1);
        if (t < 7) { storeA((t + 1) & 1); CP_WAIT0(); }
        __syncthreads();
    }

    // Epilogue
    #pragma unroll
    for (int mi = 0; mi < MI; mi++) {
        #pragma unroll
        for (int nj = 0; nj < 4; nj++) {
            int col = n0 + nj * 8 + 2 * tig;
            float b0 = biasb[col], b1 = biasb[col + 1];
            int r0 = brow + m0 + mi * 16 + gid;
            int r1 = r0 + 8;
            if (HOUT) {
                __half* C = (__half*)Cb;
                if (r0 < M)
                    *reinterpret_cast<uint32_t*>(C + (size_t)r0 * ldc + col) =
                        packh2(acc[mi][nj][0] + b0, acc[mi][nj][1] + b1);
                if (r1 < M)
                    *reinterpret_cast<uint32_t*>(C + (size_t)r1 * ldc + col) =
                        packh2(acc[mi][nj][2] + b0, acc[mi][nj][3] + b1);
            } else {
                float* C = (float*)Cb;
                if (r0 < M) {
                    float2 v0 = make_float2(acc[mi][nj][0] + b0, acc[mi][nj][1] + b1);
                    *reinterpret_cast<float2*>(C + (size_t)r0 * ldc + col) = v0;
                }
                if (r1 < M) {
                    float2 v1 = make_float2(acc[mi][nj][2] + b0, acc[mi][nj][3] + b1);
                    *reinterpret_cast<float2*>(C + (size_t)r1 * ldc + col) = v1;
                }
            }
        }
    }
}

// ---------------------------------------------------------------------------
// Fused mega-launch, 512 threads:
//   value CTAs (831): BM=128 x BN=256, 16 warps (2 x 8), MI=4
//   qproj CTAs (171): BM=128 x BN=128, 16 warps (4 x 4), MI=2
// ---------------------------------------------------------------------------
__global__ __launch_bounds__(512, 1) void gemm_fused(
    const float* __restrict__ value, const float* __restrict__ query,
    const __half* __restrict__ wt,
    const float* __restrict__ b_val, const float* __restrict__ b_off,
    const float* __restrict__ b_attn,
    __half* __restrict__ vh, float* __restrict__ qp)
{
    extern __shared__ uint32_t sm[];
    const int bid = blockIdx.x;

    if (bid < NVB) {
        gemm_tile<512, 4, 8, 256, true>(value, MV, bid * 128,
                                        wt + WT_VAL, b_val,
                                        vh, 256, sm);
    } else {
        const int q = bid - NVB;
        const int ty = q / 3, tx = q % 3;
        const __half* Bp = (tx < 2) ? (wt + WT_OFF + (size_t)tx * 128 * 256)
                                    : (wt + WT_ATTN);
        const float*  bb = (tx < 2) ? (b_off + tx * 128) : b_attn;
        gemm_tile<512, 2, 4, 128, false>(query, BQ, ty * 128,
                                         Bp, bb,
                                         qp + tx * 128, 384, sm);
    }
}

// ---------------------------------------------------------------------------
// Output projection: BM=32 (MI=1) -> 450 CTAs, ~3/SM resident.
// ---------------------------------------------------------------------------
__global__ __launch_bounds__(256, 4) void gemm_out(
    const float* __restrict__ A, const __half* __restrict__ wt,
    const float* __restrict__ bias, float* __restrict__ C)
{
    extern __shared__ uint32_t sm[];
    const int ty = blockIdx.y, tx = blockIdx.x;
    gemm_tile<256, 1, 4, 128, false>(A, BQ, ty * 32,
                                     wt + WT_OUT + (size_t)tx * 128 * 256, bias + tx * 128,
                                     C + tx * 128, 256, sm);
}

// ---------------------------------------------------------------------------
// Fused softmax + sampling over fp16 value (round-8/9 version: 29.4us).
// ---------------------------------------------------------------------------
__global__ __launch_bounds__(256) void msda_sample(
    const float* __restrict__ ref, const float* __restrict__ qp,
    const int* __restrict__ shapes, const int* __restrict__ starts,
    const __half* __restrict__ v, float* __restrict__ tmp)
{
    const int bq  = blockIdx.x;
    const int b   = bq / Qn;
    const int tid = threadIdx.x;

    __shared__ int4   sIdx[128];
    __shared__ float4 sW[128];

    if (tid < 128) {
        const int l = (tid >> 2) & 3;
        const int Hl = shapes[2 * l], Wl = shapes[2 * l + 1];
        const int st = starts[l];

        float logit = qp[(size_t)bq * 384 + 256 + tid];
        float m = logit;
        #pragma unroll
        for (int d = 8; d >= 1; d >>= 1)
            m = fmaxf(m, __shfl_xor_sync(0xffffffffu, m, d));
        float e = __expf(logit - m);
        float s = e;
        #pragma unroll
        for (int d = 8; d >= 1; d >>= 1)
            s += __shfl_xor_sync(0xffffffffu, s, d);
        const float wgt = e / s;

        const float2 off = reinterpret_cast<const float2*>(qp + (size_t)bq * 384)[tid];
        const float rx = ref[(size_t)bq * (LEVELS * 2) + 2 * l];
        const float ry = ref[(size_t)bq * (LEVELS * 2) + 2 * l + 1];
        const float x = rx * (float)Wl + off.x - 0.5f;
        const float y = ry * (float)Hl + off.y - 0.5f;

        const float x0f = floorf(x), y0f = floorf(y);
        const int x0 = (int)x0f, y0 = (int)y0f;
        const float fx = x - x0f, fy = y - y0f;
        const int x1 = x0 + 1, y1 = y0 + 1;
        const bool bx0 = (x0 >= 0) & (x0 < Wl);
        const bool bx1 = (x1 >= 0) & (x1 < Wl);
        const bool by0 = (y0 >= 0) & (y0 < Hl);
        const bool by1 = (y1 >= 0) & (y1 < Hl);
        const int cx0 = min(max(x0, 0), Wl - 1), cx1 = min(max(x1, 0), Wl - 1);
        const int cy0 = min(max(y0, 0), Hl - 1), cy1 = min(max(y1, 0), Hl - 1);

        sIdx[tid] = make_int4(st + cy0 * Wl + cx0, st + cy0 * Wl + cx1,
                              st + cy1 * Wl + cx0, st + cy1 * Wl + cx1);
        sW[tid] = make_float4(
            (bx0 && by0) ? (1.f - fx) * (1.f - fy) * wgt : 0.f,
            (bx1 && by0) ? fx * (1.f - fy) * wgt : 0.f,
            (bx0 && by1) ? (1.f - fx) * fy * wgt : 0.f,
            (bx1 && by1) ? fx * fy * wgt : 0.f);
    }
    __syncthreads();

    const int h    = tid >> 5;
    const int lane = tid & 31;
    const int sgrp = lane >> 3;
    const int c8   = lane & 7;
    const __half* vb = v + (size_t)b * NUM_KEYS * EMBED + h * HEAD_DIM + 4 * c8;

    float a0 = 0.f, a1 = 0.f, a2 = 0.f, a3 = 0.f;
    #pragma unroll
    for (int j = 0; j < 4; j++) {
        const int s = h * 16 + sgrp * 4 + j;
        const int4   id = sIdx[s];
        const float4 wv = sW[s];
        uint2 r0 = *reinterpret_cast<const uint2*>(vb + (size_t)id.x * EMBED);
        uint2 r1 = *reinterpret_cast<const uint2*>(vb + (size_t)id.y * EMBED);
        uint2 r2 = *reinterpret_cast<const uint2*>(vb + (size_t)id.z * EMBED);
        uint2 r3 = *reinterpret_cast<const uint2*>(vb + (size_t)id.w * EMBED);
        float2 g0a = __half22float2(*reinterpret_cast<__half2*>(&r0.x));
        float2 g0b = __half22float2(*reinterpret_cast<__half2*>(&r0.y));
        float2 g1a = __half22float2(*reinterpret_cast<__half2*>(&r1.x));
        float2 g1b = __half22float2(*reinterpret_cast<__half2*>(&r1.y));
        float2 g2a = __half22float2(*reinterpret_cast<__half2*>(&r2.x));
        float2 g2b = __half22float2(*reinterpret_cast<__half2*>(&r2.y));
        float2 g3a = __half22float2(*reinterpret_cast<__half2*>(&r3.x));
        float2 g3b = __half22float2(*reinterpret_cast<__half2*>(&r3.y));
        a0 = fmaf(wv.x, g0a.x, a0); a1 = fmaf(wv.x, g0a.y, a1);
        a2 = fmaf(wv.x, g0b.x, a2); a3 = fmaf(wv.x, g0b.y, a3);
        a0 = fmaf(wv.y, g1a.x, a0); a1 = fmaf(wv.y, g1a.y, a1);
        a2 = fmaf(wv.y, g1b.x, a2); a3 = fmaf(wv.y, g1b.y, a3);
        a0 = fmaf(wv.z, g2a.x, a0); a1 = fmaf(wv.z, g2a.y, a1);
        a2 = fmaf(wv.z, g2b.x, a2); a3 = fmaf(wv.z, g2b.y, a3);
        a0 = fmaf(wv.w, g3a.x, a0); a1 = fmaf(wv.w, g3a.y, a1);
        a2 = fmaf(wv.w, g3b.x, a2); a3 = fmaf(wv.w, g3b.y, a3);
    }
    #pragma unroll
    for (int d = 8; d <= 16; d <<= 1) {
        a0 += __shfl_xor_sync(0xffffffffu, a0, d);
        a1 += __shfl_xor_sync(0xffffffffu, a1, d);
        a2 += __shfl_xor_sync(0xffffffffu, a2, d);
        a3 += __shfl_xor_sync(0xffffffffu, a3, d);
    }
    if (sgrp == 0) {
        float4 o = make_float4(a0, a1, a2, a3);
        *reinterpret_cast<float4*>(tmp + (size_t)bq * 256 + h * HEAD_DIM + 4 * c8) = o;
    }
}

// ---------------------------------------------------------------------------
extern "C" void kernel_launch(void* const* d_in, const int* in_sizes, int n_in,
                              void* d_out, int out_size)
{
    const float* query  = (const float*)d_in[0];
    const float* refpts = (const float*)d_in[1];
    const float* value  = (const float*)d_in[2];
    const int*   shapes = (const int*)  d_in[3];
    const int*   starts = (const int*)  d_in[4];
    const float* W_off  = (const float*)d_in[5];
    const float* b_off  = (const float*)d_in[6];
    const float* W_attn = (const float*)d_in[7];
    const float* b_attn = (const float*)d_in[8];
    const float* W_val  = (const float*)d_in[9];
    const float* b_val  = (const float*)d_in[10];
    const float* W_out  = (const float*)d_in[11];
    const float* b_out  = (const float*)d_in[12];
    float* out = (float*)d_out;

    __half *pvh, *pwt;
    float *pqp, *ptmp;
    cudaGetSymbolAddress((void**)&pvh,  g_vh);
    cudaGetSymbolAddress((void**)&pqp,  g_qp);
    cudaGetSymbolAddress((void**)&ptmp, g_tmp);
    cudaGetSymbolAddress((void**)&pwt,  g_wt);

    const int SMEMF = 2 * (128 * 20 + 256 * 20) * 4;   // 61440 B (value branch max)
    const int SMEMO = 2 * ( 32 * 20 + 128 * 20) * 4;   // 25600 B
    cudaFuncSetAttribute(gemm_fused, cudaFuncAttributeMaxDynamicSharedMemorySize, SMEMF);
    cudaFuncSetAttribute(gemm_out,   cudaFuncAttributeMaxDynamicSharedMemorySize, SMEMO);

    // 0) transpose+convert all weights to fp16 [n][k]
    transpose_w<<<dim3(8, 8, 4), dim3(32, 8)>>>(W_val, W_off, W_attn, W_out, pwt);
    // 1) value projection (fp16 out) + combined query projection, one launch
    gemm_fused<<<NVB + NQB, 512, SMEMF>>>(value, query, pwt,
                                          b_val, b_off, b_attn, pvh, pqp);
    // 2) fused softmax + sampling
    msda_sample<<<BQ, 256>>>(refpts, pqp, shapes, starts, pvh, ptmp);
    // 3) output projection: [7200,256] @ [256,256], BM=32
    {
        dim3 grid(2, (BQ + 31) / 32);
        gemm_out<<<grid, 256, SMEMO>>>(ptmp, pwt, b_out, out);
    }
}

// round 15
// speedup vs baseline: 1.0543x; 1.0543x over previous
#include <cuda_runtime.h>
#include <cuda_fp16.h>
#include <cstdint>

// Problem constants
#define Bn 8
#define Qn 900
#define EMBED 256
#define HEADS 8
#define LEVELS 4
#define POINTS 4
#define HEAD_DIM 32
#define NUM_KEYS 13294
#define BQ (Bn*Qn)            // 7200
#define MV (Bn*NUM_KEYS)      // 106352

#define NVB_Y ((MV + 127) / 128)      // 831 value row-tiles (BM=128)
#define NVB   (NVB_Y * 2)             // 1662 value CTAs
#define NQB_Y ((BQ + 63) / 64)        // 113 query row-tiles (BM=64)
#define NQB   (NQB_Y * 3)             // 339 qproj CTAs

// Transposed fp16 weight regions within g_wt (units: halfs)
#define WT_VAL  0
#define WT_OFF  65536
#define WT_ATTN 131072
#define WT_OUT  163840

// Scratch (device globals; no runtime allocation)
__device__ __half g_vh  [(size_t)MV * EMBED];  // projected value, fp16
__device__ float  g_qp  [(size_t)BQ * 384];    // [off(256) | attn(128)] per query
__device__ __half g_tmph[(size_t)BQ * 256];    // msda output, fp16
__device__ __half g_wt  [229376];              // all weights, [n][k] fp16

__device__ __forceinline__ uint32_t packh2(float a, float b) {
    __half2 h = __floats2half2_rn(a, b);
    return *reinterpret_cast<uint32_t*>(&h);
}
__device__ __forceinline__ uint32_t smem_u32(const void* p) {
    uint32_t a;
    asm("{ .reg .u64 t; cvta.to.shared.u64 t, %1; cvt.u32.u64 %0, t; }"
        : "=r"(a) : "l"(p));
    return a;
}
__device__ __forceinline__ void ldsm_x4(uint32_t& r0, uint32_t& r1,
                                        uint32_t& r2, uint32_t& r3, uint32_t addr) {
    asm volatile("ldmatrix.sync.aligned.m8n8.x4.shared.b16 {%0,%1,%2,%3}, [%4];"
                 : "=r"(r0), "=r"(r1), "=r"(r2), "=r"(r3) : "r"(addr));
}
__device__ __forceinline__ void cp_async16(uint32_t dst, const void* src) {
    asm volatile("cp.async.cg.shared.global [%0], [%1], 16;"
                 :: "r"(dst), "l"(src) : "memory");
}
#define CP_COMMIT() asm volatile("cp.async.commit_group;" ::: "memory")
#define CP_WAIT0()  asm volatile("cp.async.wait_group 0;" ::: "memory")

#define HMMA16816(acc, a, b) \
    asm volatile( \
        "mma.sync.aligned.m16n8k16.row.col.f32.f16.f16.f32 " \
        "{%0,%1,%2,%3}, {%4,%5,%6,%7}, {%8,%9}, {%0,%1,%2,%3};" \
        : "+f"((acc)[0]), "+f"((acc)[1]), "+f"((acc)[2]), "+f"((acc)[3]) \
        : "r"((a)[0]), "r"((a)[1]), "r"((a)[2]), "r"((a)[3]), \
          "r"((b)[0]), "r"((b)[1]))

// ---------------------------------------------------------------------------
// Weight transpose+convert: W[k][n] f32 -> Wt[n][k] f16 (rounding == packh2).
// ---------------------------------------------------------------------------
__global__ void transpose_w(const float* __restrict__ W_val,
                            const float* __restrict__ W_off,
                            const float* __restrict__ W_attn,
                            const float* __restrict__ W_out,
                            __half* __restrict__ Wt)
{
    const float* W; int N; int base;
    switch (blockIdx.z) {
        case 0:  W = W_val;  N = 256; base = WT_VAL;  break;
        case 1:  W = W_off;  N = 256; base = WT_OFF;  break;
        case 2:  W = W_attn; N = 128; base = WT_ATTN; break;
        default: W = W_out;  N = 256; base = WT_OUT;  break;
    }
    const int n0 = blockIdx.x * 32, k0 = blockIdx.y * 32;
    if (n0 >= N) return;

    __shared__ float t[32][33];
    const int tx = threadIdx.x, ty = threadIdx.y;
    #pragma unroll
    for (int i = 0; i < 4; i++)
        t[tx][ty + 8 * i] = W[(size_t)(k0 + ty + 8 * i) * N + n0 + tx];
    __syncthreads();
    const int id = ty * 32 + tx;
    #pragma unroll
    for (int i = 0; i < 2; i++) {
        int e = id + i * 256, n = e >> 4, kk = e & 15;
        uint32_t h = packh2(t[n][2 * kk], t[n][2 * kk + 1]);
        *reinterpret_cast<uint32_t*>(Wt + base + (size_t)(n0 + n) * 256 + k0 + 2 * kk) = h;
    }
}

// ---------------------------------------------------------------------------
// Round-12 GEMM core (validated best): 256 threads, warp grid 2x4,
// warp tile (MI*16)x32, CTA tile (MI*32)x128, K=256 in 8 double-buffered
// BK=32 stages, 1 sync per stage.
// ---------------------------------------------------------------------------
template <int MI, bool HOUT>
__device__ __forceinline__ void gemm_tile(
    const float* __restrict__ A, int M, int brow,
    const __half* __restrict__ Bt,
    const float* __restrict__ biasb,
    void* __restrict__ Cb,
    int ldc,
    uint32_t* sm)
{
    constexpr int BM    = MI * 32;
    constexpr int AST   = 20;
    constexpr int ASZW  = BM * AST;
    constexpr int ASZB  = ASZW * 4;
    constexpr int BSZW  = 128 * AST;
    constexpr int STGW  = ASZW + BSZW;
    constexpr int STGB  = STGW * 4;

    const int tid  = threadIdx.x;
    const int lane = tid & 31;
    const int w    = tid >> 5;
    const int gid  = lane >> 2;
    const int tig  = lane & 3;
    const int m0   = (w >> 2) * (MI * 16);
    const int n0   = (w & 3) * 32;

    const uint32_t smbase = smem_u32(sm);
    const uint32_t aAddr = smbase + (uint32_t)(m0 + (lane & 15)) * 80
                                  + ((lane & 16) ? 16u : 0u);
    const uint32_t bAddr = smbase + ASZB
                                  + (uint32_t)(n0 + (lane & 7) + ((lane & 16) ? 8 : 0)) * 80
                                  + ((lane & 8) ? 16u : 0u);

    float acc[MI][4][4];
    #pragma unroll
    for (int mi = 0; mi < MI; mi++)
        #pragma unroll
        for (int nj = 0; nj < 4; nj++)
            #pragma unroll
            for (int r = 0; r < 4; r++) acc[mi][nj][r] = 0.f;

    float4 pa[MI];

    auto issueB = [&](int t, int p) {
        const int k0 = t * 32;
        #pragma unroll
        for (int i = 0; i < 2; ++i) {
            int g = tid + i * 256, n = g >> 2, ch = g & 3;
            uint32_t dst = smbase + (uint32_t)p * STGB + ASZB + (uint32_t)n * 80 + ch * 16;
            cp_async16(dst, Bt + (size_t)n * 256 + k0 + ch * 8);
        }
        CP_COMMIT();
    };
    auto loadA = [&](int k0) {
        #pragma unroll
        for (int i = 0; i < MI; ++i) {
            int c = tid + i * 256, row = c >> 3, slot = c & 7;
            int gr = min(brow + row, M - 1);
            pa[i] = *reinterpret_cast<const float4*>(A + (size_t)gr * 256 + k0 + slot * 4);
        }
    };
    auto storeA = [&](int p) {
        uint32_t* As = sm + p * STGW;
        #pragma unroll
        for (int i = 0; i < MI; ++i) {
            int c = tid + i * 256, row = c >> 3, slot = c & 7;
            uint2 t = { packh2(pa[i].x, pa[i].y), packh2(pa[i].z, pa[i].w) };
            *reinterpret_cast<uint2*>(&As[row * AST + 2 * slot]) = t;
        }
    };
    auto compute = [&](int p) {
        const uint32_t pb = (uint32_t)p * STGB;
        #pragma unroll
        for (int ks = 0; ks < 2; ks++) {
            uint32_t a[MI][4], b[4][2];
            #pragma unroll
            for (int mi = 0; mi < MI; mi++)
                ldsm_x4(a[mi][0], a[mi][1], a[mi][2], a[mi][3],
                        aAddr + pb + mi * 1280 + ks * 32);
            #pragma unroll
            for (int njp = 0; njp < 2; njp++)
                ldsm_x4(b[2 * njp][0], b[2 * njp][1], b[2 * njp + 1][0], b[2 * njp + 1][1],
                        bAddr + pb + njp * 1280 + ks * 32);
            #pragma unroll
            for (int mi = 0; mi < MI; mi++)
                #pragma unroll
                for (int nj = 0; nj < 4; nj++)
                    HMMA16816(acc[mi][nj], a[mi], b[nj]);
        }
    };

    issueB(0, 0);
    loadA(0);
    storeA(0);
    CP_WAIT0();
    __syncthreads();
    #pragma unroll 1
    for (int t = 0; t < 8; t++) {
        if (t < 7) { issueB(t + 1, (t + 1) & 1); loadA((t + 1) * 32); }
        compute(t & 1);
        if (t < 7) { storeA((t + 1) & 1); CP_WAIT0(); }
        __syncthreads();
    }

    // Epilogue
    #pragma unroll
    for (int mi = 0; mi < MI; mi++) {
        #pragma unroll
        for (int nj = 0; nj < 4; nj++) {
            int col = n0 + nj * 8 + 2 * tig;
            float b0 = biasb[col], b1 = biasb[col + 1];
            int r0 = brow + m0 + mi * 16 + gid;
            int r1 = r0 + 8;
            if (HOUT) {
                __half* C = (__half*)Cb;
                if (r0 < M)
                    *reinterpret_cast<uint32_t*>(C + (size_t)r0 * ldc + col) =
                        packh2(acc[mi][nj][0] + b0, acc[mi][nj][1] + b1);
                if (r1 < M)
                    *reinterpret_cast<uint32_t*>(C + (size_t)r1 * ldc + col) =
                        packh2(acc[mi][nj][2] + b0, acc[mi][nj][3] + b1);
            } else {
                float* C = (float*)Cb;
                if (r0 < M) {
                    float2 v0 = make_float2(acc[mi][nj][0] + b0, acc[mi][nj][1] + b1);
                    *reinterpret_cast<float2*>(C + (size_t)r0 * ldc + col) = v0;
                }
                if (r1 < M) {
                    float2 v1 = make_float2(acc[mi][nj][2] + b0, acc[mi][nj][3] + b1);
                    *reinterpret_cast<float2*>(C + (size_t)r1 * ldc + col) = v1;
                }
            }
        }
    }
}

// ---------------------------------------------------------------------------
// Fused mega-launch (round-12 config): value (1662 CTAs, BM=128) +
// query projections (339 CTAs, BM=64).
// ---------------------------------------------------------------------------
__global__ __launch_bounds__(256, 2) void gemm_fused(
    const float* __restrict__ value, const float* __restrict__ query,
    const __half* __restrict__ wt,
    const float* __restrict__ b_val, const float* __restrict__ b_off,
    const float* __restrict__ b_attn,
    __half* __restrict__ vh, float* __restrict__ qp)
{
    extern __shared__ uint32_t sm[];
    const int bid = blockIdx.x;

    if (bid < NVB) {
        const int ty = bid >> 1, tx = bid & 1;
        gemm_tile<4, true>(value, MV, ty * 128,
                           wt + WT_VAL + (size_t)tx * 128 * 256, b_val + tx * 128,
                           vh + tx * 128, 256, sm);
    } else {
        const int q = bid - NVB;
        const int ty = q / 3, tx = q % 3;
        const __half* Bp = (tx < 2) ? (wt + WT_OFF + (size_t)tx * 128 * 256)
                                    : (wt + WT_ATTN);
        const float*  bb = (tx < 2) ? (b_off + tx * 128) : b_attn;
        gemm_tile<2, false>(query, BQ, ty * 64,
                            Bp, bb,
                            qp + tx * 128, 384, sm);
    }
}

// ---------------------------------------------------------------------------
// Output projection: single-stage full-K. BM=64 x BN=128, K=256.
// Smem rows hold all 256 halfs = 512B of data, stride 528B (132 words;
// bank walk 4r conflict-free). One cp.async burst (A fp16 tmp: 8/thread,
// B fp16 weights: 16/thread; 32 x 16B chunks per row), one wait+sync,
// then 16 uninterrupted ldmatrix+HMMA k-steps.
// ---------------------------------------------------------------------------
__global__ __launch_bounds__(256, 2) void gemm_out(
    const __half* __restrict__ A,      // tmp fp16 [BQ][256]
    const __half* __restrict__ wt, const float* __restrict__ bias,
    float* __restrict__ C)
{
    constexpr int RSTB = 528;              // bytes per smem row
    constexpr int ASZB = 64 * RSTB;        // 33792 B

    extern __shared__ uint32_t sm[];
    const int tid  = threadIdx.x;
    const int lane = tid & 31;
    const int w    = tid >> 5;
    const int gid  = lane >> 2;
    const int tig  = lane & 3;
    const int brow = blockIdx.y * 64;
    const int txb  = blockIdx.x;
    const __half* Bt = wt + WT_OUT + (size_t)txb * 128 * 256;
    const int m0 = (w >> 2) * 32;          // 2 warp rows, MI=2
    const int n0 = (w & 3) * 32;

    const uint32_t smbase = smem_u32(sm);

    // A: 64 rows x 32 16B-chunks = 2048 cp.async -> 8/thread
    #pragma unroll
    for (int i = 0; i < 8; i++) {
        int g = tid + i * 256, row = g >> 5, ch = g & 31;
        int gr = min(brow + row, BQ - 1);
        cp_async16(smbase + (uint32_t)row * RSTB + ch * 16,
                   A + (size_t)gr * 256 + ch * 8);
    }
    // B: 128 rows x 32 chunks = 4096 -> 16/thread
    #pragma unroll
    for (int i = 0; i < 16; i++) {
        int g = tid + i * 256, n = g >> 5, ch = g & 31;
        cp_async16(smbase + ASZB + (uint32_t)n * RSTB + ch * 16,
                   Bt + (size_t)n * 256 + ch * 8);
    }
    CP_COMMIT();
    CP_WAIT0();
    __syncthreads();

    const uint32_t aAddr = smbase + (uint32_t)(m0 + (lane & 15)) * RSTB
                                  + ((lane & 16) ? 16u : 0u);
    const uint32_t bAddr = smbase + ASZB
                                  + (uint32_t)(n0 + (lane & 7) + ((lane & 16) ? 8 : 0)) * RSTB
                                  + ((lane & 8) ? 16u : 0u);

    float acc[2][4][4];
    #pragma unroll
    for (int mi = 0; mi < 2; mi++)
        #pragma unroll
        for (int nj = 0; nj < 4; nj++)
            #pragma unroll
            for (int r = 0; r < 4; r++) acc[mi][nj][r] = 0.f;

    #pragma unroll
    for (int kk = 0; kk < 16; kk++) {      // 16 x k-groups of 16 halfs (32B)
        uint32_t a[2][4], b[4][2];
        #pragma unroll
        for (int mi = 0; mi < 2; mi++)
            ldsm_x4(a[mi][0], a[mi][1], a[mi][2], a[mi][3],
                    aAddr + mi * 16 * RSTB + kk * 32);
        #pragma unroll
        for (int njp = 0; njp < 2; njp++)
            ldsm_x4(b[2 * njp][0], b[2 * njp][1], b[2 * njp + 1][0], b[2 * njp + 1][1],
                    bAddr + njp * 16 * RSTB + kk * 32);
        #pragma unroll
        for (int mi = 0; mi < 2; mi++)
            #pragma unroll
            for (int nj = 0; nj < 4; nj++)
                HMMA16816(acc[mi][nj], a[mi], b[nj]);
    }

    #pragma unroll
    for (int mi = 0; mi < 2; mi++) {
        #pragma unroll
        for (int nj = 0; nj < 4; nj++) {
            int col = txb * 128 + n0 + nj * 8 + 2 * tig;
            float b0 = bias[col], b1 = bias[col + 1];
            int r0 = brow + m0 + mi * 16 + gid;
            int r1 = r0 + 8;
            if (r0 < BQ) {
                float2 v0 = make_float2(acc[mi][nj][0] + b0, acc[mi][nj][1] + b1);
                *reinterpret_cast<float2*>(C + (size_t)r0 * 256 + col) = v0;
            }
            if (r1 < BQ) {
                float2 v1 = make_float2(acc[mi][nj][2] + b0, acc[mi][nj][3] + b1);
                *reinterpret_cast<float2*>(C + (size_t)r1 * 256 + col) = v1;
            }
        }
    }
}

// ---------------------------------------------------------------------------
// Fused softmax + sampling over fp16 value; writes tmp as fp16.
// ---------------------------------------------------------------------------
__global__ __launch_bounds__(256) void msda_sample(
    const float* __restrict__ ref, const float* __restrict__ qp,
    const int* __restrict__ shapes, const int* __restrict__ starts,
    const __half* __restrict__ v, __half* __restrict__ tmp)
{
    const int bq  = blockIdx.x;
    const int b   = bq / Qn;
    const int tid = threadIdx.x;

    __shared__ int4   sIdx[128];
    __shared__ float4 sW[128];

    if (tid < 128) {
        const int l = (tid >> 2) & 3;
        const int Hl = shapes[2 * l], Wl = shapes[2 * l + 1];
        const int st = starts[l];

        float logit = qp[(size_t)bq * 384 + 256 + tid];
        float m = logit;
        #pragma unroll
        for (int d = 8; d >= 1; d >>= 1)
            m = fmaxf(m, __shfl_xor_sync(0xffffffffu, m, d));
        float e = __expf(logit - m);
        float s = e;
        #pragma unroll
        for (int d = 8; d >= 1; d >>= 1)
            s += __shfl_xor_sync(0xffffffffu, s, d);
        const float wgt = e / s;

        const float2 off = reinterpret_cast<const float2*>(qp + (size_t)bq * 384)[tid];
        const float rx = ref[(size_t)bq * (LEVELS * 2) + 2 * l];
        const float ry = ref[(size_t)bq * (LEVELS * 2) + 2 * l + 1];
        const float x = rx * (float)Wl + off.x - 0.5f;
        const float y = ry * (float)Hl + off.y - 0.5f;

        const float x0f = floorf(x), y0f = floorf(y);
        const int x0 = (int)x0f, y0 = (int)y0f;
        const float fx = x - x0f, fy = y - y0f;
        const int x1 = x0 + 1, y1 = y0 + 1;
        const bool bx0 = (x0 >= 0) & (x0 < Wl);
        const bool bx1 = (x1 >= 0) & (x1 < Wl);
        const bool by0 = (y0 >= 0) & (y0 < Hl);
        const bool by1 = (y1 >= 0) & (y1 < Hl);
        const int cx0 = min(max(x0, 0), Wl - 1), cx1 = min(max(x1, 0), Wl - 1);
        const int cy0 = min(max(y0, 0), Hl - 1), cy1 = min(max(y1, 0), Hl - 1);

        sIdx[tid] = make_int4(st + cy0 * Wl + cx0, st + cy0 * Wl + cx1,
                              st + cy1 * Wl + cx0, st + cy1 * Wl + cx1);
        sW[tid] = make_float4(
            (bx0 && by0) ? (1.f - fx) * (1.f - fy) * wgt : 0.f,
            (bx1 && by0) ? fx * (1.f - fy) * wgt : 0.f,
            (bx0 && by1) ? (1.f - fx) * fy * wgt : 0.f,
            (bx1 && by1) ? fx * fy * wgt : 0.f);
    }
    __syncthreads();

    const int h    = tid >> 5;
    const int lane = tid & 31;
    const int sgrp = lane >> 3;
    const int c8   = lane & 7;
    const __half* vb = v + (size_t)b * NUM_KEYS * EMBED + h * HEAD_DIM + 4 * c8;

    float a0 = 0.f, a1 = 0.f, a2 = 0.f, a3 = 0.f;
    #pragma unroll
    for (int j = 0; j < 4; j++) {
        const int s = h * 16 + sgrp * 4 + j;
        const int4   id = sIdx[s];
        const float4 wv = sW[s];
        uint2 r0 = *reinterpret_cast<const uint2*>(vb + (size_t)id.x * EMBED);
        uint2 r1 = *reinterpret_cast<const uint2*>(vb + (size_t)id.y * EMBED);
        uint2 r2 = *reinterpret_cast<const uint2*>(vb + (size_t)id.z * EMBED);
        uint2 r3 = *reinterpret_cast<const uint2*>(vb + (size_t)id.w * EMBED);
        float2 g0a = __half22float2(*reinterpret_cast<__half2*>(&r0.x));
        float2 g0b = __half22float2(*reinterpret_cast<__half2*>(&r0.y));
        float2 g1a = __half22float2(*reinterpret_cast<__half2*>(&r1.x));
        float2 g1b = __half22float2(*reinterpret_cast<__half2*>(&r1.y));
        float2 g2a = __half22float2(*reinterpret_cast<__half2*>(&r2.x));
        float2 g2b = __half22float2(*reinterpret_cast<__half2*>(&r2.y));
        float2 g3a = __half22float2(*reinterpret_cast<__half2*>(&r3.x));
        float2 g3b = __half22float2(*reinterpret_cast<__half2*>(&r3.y));
        a0 = fmaf(wv.x, g0a.x, a0); a1 = fmaf(wv.x, g0a.y, a1);
        a2 = fmaf(wv.x, g0b.x, a2); a3 = fmaf(wv.x, g0b.y, a3);
        a0 = fmaf(wv.y, g1a.x, a0); a1 = fmaf(wv.y, g1a.y, a1);
        a2 = fmaf(wv.y, g1b.x, a2); a3 = fmaf(wv.y, g1b.y, a3);
        a0 = fmaf(wv.z, g2a.x, a0); a1 = fmaf(wv.z, g2a.y, a1);
        a2 = fmaf(wv.z, g2b.x, a2); a3 = fmaf(wv.z, g2b.y, a3);
        a0 = fmaf(wv.w, g3a.x, a0); a1 = fmaf(wv.w, g3a.y, a1);
        a2 = fmaf(wv.w, g3b.x, a2); a3 = fmaf(wv.w, g3b.y, a3);
    }
    #pragma unroll
    for (int d = 8; d <= 16; d <<= 1) {
        a0 += __shfl_xor_sync(0xffffffffu, a0, d);
        a1 += __shfl_xor_sync(0xffffffffu, a1, d);
        a2 += __shfl_xor_sync(0xffffffffu, a2, d);
        a3 += __shfl_xor_sync(0xffffffffu, a3, d);
    }
    if (sgrp == 0) {
        uint2 o = { packh2(a0, a1), packh2(a2, a3) };
        *reinterpret_cast<uint2*>(tmp + (size_t)bq * 256 + h * HEAD_DIM + 4 * c8) = o;
    }
}

// ---------------------------------------------------------------------------
extern "C" void kernel_launch(void* const* d_in, const int* in_sizes, int n_in,
                              void* d_out, int out_size)
{
    const float* query  = (const float*)d_in[0];
    const float* refpts = (const float*)d_in[1];
    const float* value  = (const float*)d_in[2];
    const int*   shapes = (const int*)  d_in[3];
    const int*   starts = (const int*)  d_in[4];
    const float* W_off  = (const float*)d_in[5];
    const float* b_off  = (const float*)d_in[6];
    const float* W_attn = (const float*)d_in[7];
    const float* b_attn = (const float*)d_in[8];
    const float* W_val  = (const float*)d_in[9];
    const float* b_val  = (const float*)d_in[10];
    const float* W_out  = (const float*)d_in[11];
    const float* b_out  = (const float*)d_in[12];
    float* out = (float*)d_out;

    __half *pvh, *pwt, *ptmph;
    float *pqp;
    cudaGetSymbolAddress((void**)&pvh,   g_vh);
    cudaGetSymbolAddress((void**)&pqp,   g_qp);
    cudaGetSymbolAddress((void**)&ptmph, g_tmph);
    cudaGetSymbolAddress((void**)&pwt,   g_wt);

    const int SMEMF = 2 * (128 * 20 + 128 * 20) * 4;   // 40960 B (value branch)
    const int SMEMO = (64 + 128) * 528;                // 101376 B
    cudaFuncSetAttribute(gemm_fused, cudaFuncAttributeMaxDynamicSharedMemorySize, SMEMF);
    cudaFuncSetAttribute(gemm_out,   cudaFuncAttributeMaxDynamicSharedMemorySize, SMEMO);

    // 0) transpose+convert all weights to fp16 [n][k]
    transpose_w<<<dim3(8, 8, 4), dim3(32, 8)>>>(W_val, W_off, W_attn, W_out, pwt);
    // 1) value projection (fp16 out) + combined query projection, one launch
    gemm_fused<<<NVB + NQB, 256, SMEMF>>>(value, query, pwt,
                                          b_val, b_off, b_attn, pvh, pqp);
    // 2) fused softmax + sampling -> fp16 tmp
    msda_sample<<<BQ, 256>>>(refpts, pqp, shapes, starts, pvh, ptmph);
    // 3) output projection: single-stage, [7200,256] @ [256,256]
    {
        dim3 grid(2, NQB_Y);
        gemm_out<<<grid, 256, SMEMO>>>(ptmph, pwt, b_out, out);
    }
}

// round 16
// speedup vs baseline: 1.0759x; 1.0205x over previous
#include <cuda_runtime.h>
#include <cuda_fp16.h>
#include <cstdint>

// Problem constants
#define Bn 8
#define Qn 900
#define EMBED 256
#define HEADS 8
#define LEVELS 4
#define POINTS 4
#define HEAD_DIM 32
#define NUM_KEYS 13294
#define BQ (Bn*Qn)            // 7200
#define MV (Bn*NUM_KEYS)      // 106352

#define NVB_Y ((MV + 127) / 128)      // 831 value row-tiles (BM=128)
#define NVB   (NVB_Y * 2)             // 1662 value CTAs
#define NQB_Y ((BQ + 63) / 64)        // 113 query row-tiles (BM=64)
#define NQB   (NQB_Y * 3)             // 339 qproj CTAs

// Transposed fp16 weight regions within g_wt (units: halfs)
#define WT_VAL  0
#define WT_OFF  65536
#define WT_ATTN 131072
#define WT_OUT  163840

// Scratch (device globals; no runtime allocation)
__device__ __half g_vh  [(size_t)MV * EMBED];  // projected value, fp16
__device__ float  g_qp  [(size_t)BQ * 384];    // [off(256) | attn(128)] per query
__device__ __half g_tmph[(size_t)BQ * 256];    // msda output, fp16
__device__ __half g_wt  [229376];              // all weights, [n][k] fp16

__device__ __forceinline__ uint32_t packh2(float a, float b) {
    __half2 h = __floats2half2_rn(a, b);
    return *reinterpret_cast<uint32_t*>(&h);
}
__device__ __forceinline__ uint32_t smem_u32(const void* p) {
    uint32_t a;
    asm("{ .reg .u64 t; cvta.to.shared.u64 t, %1; cvt.u32.u64 %0, t; }"
        : "=r"(a) : "l"(p));
    return a;
}
__device__ __forceinline__ void ldsm_x4(uint32_t& r0, uint32_t& r1,
                                        uint32_t& r2, uint32_t& r3, uint32_t addr) {
    asm volatile("ldmatrix.sync.aligned.m8n8.x4.shared.b16 {%0,%1,%2,%3}, [%4];"
                 : "=r"(r0), "=r"(r1), "=r"(r2), "=r"(r3) : "r"(addr));
}
__device__ __forceinline__ void cp_async16(uint32_t dst, const void* src) {
    asm volatile("cp.async.cg.shared.global [%0], [%1], 16;"
                 :: "r"(dst), "l"(src) : "memory");
}
#define CP_COMMIT() asm volatile("cp.async.commit_group;" ::: "memory")
#define CP_WAIT0()  asm volatile("cp.async.wait_group 0;" ::: "memory")
#define CP_WAIT1()  asm volatile("cp.async.wait_group 1;" ::: "memory")

#define HMMA16816(acc, a, b) \
    asm volatile( \
        "mma.sync.aligned.m16n8k16.row.col.f32.f16.f16.f32 " \
        "{%0,%1,%2,%3}, {%4,%5,%6,%7}, {%8,%9}, {%0,%1,%2,%3};" \
        : "+f"((acc)[0]), "+f"((acc)[1]), "+f"((acc)[2]), "+f"((acc)[3]) \
        : "r"((a)[0]), "r"((a)[1]), "r"((a)[2]), "r"((a)[3]), \
          "r"((b)[0]), "r"((b)[1]))

// ---------------------------------------------------------------------------
// Weight transpose+convert: W[k][n] f32 -> Wt[n][k] f16 (rounding == packh2).
// ---------------------------------------------------------------------------
__global__ void transpose_w(const float* __restrict__ W_val,
                            const float* __restrict__ W_off,
                            const float* __restrict__ W_attn,
                            const float* __restrict__ W_out,
                            __half* __restrict__ Wt)
{
    const float* W; int N; int base;
    switch (blockIdx.z) {
        case 0:  W = W_val;  N = 256; base = WT_VAL;  break;
        case 1:  W = W_off;  N = 256; base = WT_OFF;  break;
        case 2:  W = W_attn; N = 128; base = WT_ATTN; break;
        default: W = W_out;  N = 256; base = WT_OUT;  break;
    }
    const int n0 = blockIdx.x * 32, k0 = blockIdx.y * 32;
    if (n0 >= N) return;

    __shared__ float t[32][33];
    const int tx = threadIdx.x, ty = threadIdx.y;
    #pragma unroll
    for (int i = 0; i < 4; i++)
        t[tx][ty + 8 * i] = W[(size_t)(k0 + ty + 8 * i) * N + n0 + tx];
    __syncthreads();
    const int id = ty * 32 + tx;
    #pragma unroll
    for (int i = 0; i < 2; i++) {
        int e = id + i * 256, n = e >> 4, kk = e & 15;
        uint32_t h = packh2(t[n][2 * kk], t[n][2 * kk + 1]);
        *reinterpret_cast<uint32_t*>(Wt + base + (size_t)(n0 + n) * 256 + k0 + 2 * kk) = h;
    }
}

// ---------------------------------------------------------------------------
// GEMM core: 256 threads, warp grid 2x4, warp tile (MI*16)x32,
// CTA tile (MI*32)x128, K=256 in 8 BK=32 stages.
// A: fp32 gmem -> regs -> cvt -> smem (2 buffers), ldmatrix.x4 fragments.
// B: fp16 [n][k] gmem -> cp.async -> smem (3 buffers, wait_group 1 so each
//    B load has a full iteration of compute to land), ldmatrix.x4 fragments.
// ---------------------------------------------------------------------------
template <int MI, bool HOUT>
__device__ __forceinline__ void gemm_tile(
    const float* __restrict__ A, int M, int brow,
    const __half* __restrict__ Bt,
    const float* __restrict__ biasb,
    void* __restrict__ Cb,
    int ldc,
    uint32_t* sm)
{
    constexpr int BM    = MI * 32;
    constexpr int AST   = 20;
    constexpr int ASZW  = BM * AST;    // A words per buffer
    constexpr int ASZB  = ASZW * 4;
    constexpr int BSZW  = 128 * AST;   // B words per buffer
    constexpr int BSZB  = BSZW * 4;    // 10240
    // layout: A0 A1 | B0 B1 B2
    const int boffW = 2 * ASZW;

    const int tid  = threadIdx.x;
    const int lane = tid & 31;
    const int w    = tid >> 5;
    const int gid  = lane >> 2;
    const int tig  = lane & 3;
    const int m0   = (w >> 2) * (MI * 16);
    const int n0   = (w & 3) * 32;

    const uint32_t smbase = smem_u32(sm);
    const uint32_t aAddr = smbase + (uint32_t)(m0 + (lane & 15)) * 80
                                  + ((lane & 16) ? 16u : 0u);
    const uint32_t bAddr = smbase + (uint32_t)(2 * ASZB)
                                  + (uint32_t)(n0 + (lane & 7) + ((lane & 16) ? 8 : 0)) * 80
                                  + ((lane & 8) ? 16u : 0u);

    float acc[MI][4][4];
    #pragma unroll
    for (int mi = 0; mi < MI; mi++)
        #pragma unroll
        for (int nj = 0; nj < 4; nj++)
            #pragma unroll
            for (int r = 0; r < 4; r++) acc[mi][nj][r] = 0.f;

    float4 pa[MI];

    auto issueB = [&](int t) {
        const int k0 = t * 32;
        const int buf = t % 3;
        #pragma unroll
        for (int i = 0; i < 2; ++i) {
            int g = tid + i * 256, n = g >> 2, ch = g & 3;
            uint32_t dst = smbase + 2 * ASZB + (uint32_t)buf * BSZB
                         + (uint32_t)n * 80 + ch * 16;
            cp_async16(dst, Bt + (size_t)n * 256 + k0 + ch * 8);
        }
        CP_COMMIT();
    };
    auto loadA = [&](int k0) {
        #pragma unroll
        for (int i = 0; i < MI; ++i) {
            int c = tid + i * 256, row = c >> 3, slot = c & 7;
            int gr = min(brow + row, M - 1);
            pa[i] = *reinterpret_cast<const float4*>(A + (size_t)gr * 256 + k0 + slot * 4);
        }
    };
    auto storeA = [&](int p) {
        uint32_t* As = sm + p * ASZW;
        #pragma unroll
        for (int i = 0; i < MI; ++i) {
            int c = tid + i * 256, row = c >> 3, slot = c & 7;
            uint2 t = { packh2(pa[i].x, pa[i].y), packh2(pa[i].z, pa[i].w) };
            *reinterpret_cast<uint2*>(&As[row * AST + 2 * slot]) = t;
        }
    };
    auto compute = [&](int t) {
        const uint32_t pa_off = (uint32_t)(t & 1) * ASZB;
        const uint32_t pb_off = (uint32_t)(t % 3) * BSZB;
        #pragma unroll
        for (int ks = 0; ks < 2; ks++) {
            uint32_t a[MI][4], b[4][2];
            #pragma unroll
            for (int mi = 0; mi < MI; mi++)
                ldsm_x4(a[mi][0], a[mi][1], a[mi][2], a[mi][3],
                        aAddr + pa_off + mi * 1280 + ks * 32);
            #pragma unroll
            for (int njp = 0; njp < 2; njp++)
                ldsm_x4(b[2 * njp][0], b[2 * njp][1], b[2 * njp + 1][0], b[2 * njp + 1][1],
                        bAddr + pb_off + njp * 1280 + ks * 32);
            #pragma unroll
            for (int mi = 0; mi < MI; mi++)
                #pragma unroll
                for (int nj = 0; nj < 4; nj++)
                    HMMA16816(acc[mi][nj], a[mi], b[nj]);
        }
    };

    // prologue: B0, B1 in flight; A0 staged. Wait B0 only (one group may remain).
    issueB(0);
    issueB(1);
    loadA(0);
    storeA(0);
    CP_WAIT1();
    __syncthreads();
    #pragma unroll 1
    for (int t = 0; t < 8; t++) {
        if (t < 6) issueB(t + 2);
        if (t < 7) loadA((t + 1) * 32);
        compute(t);
        if (t < 7) storeA((t + 1) & 1);
        if (t < 6) CP_WAIT1();
        else if (t == 6) CP_WAIT0();
        __syncthreads();
    }

    // Epilogue
    #pragma unroll
    for (int mi = 0; mi < MI; mi++) {
        #pragma unroll
        for (int nj = 0; nj < 4; nj++) {
            int col = n0 + nj * 8 + 2 * tig;
            float b0 = biasb[col], b1 = biasb[col + 1];
            int r0 = brow + m0 + mi * 16 + gid;
            int r1 = r0 + 8;
            if (HOUT) {
                __half* C = (__half*)Cb;
                if (r0 < M)
                    *reinterpret_cast<uint32_t*>(C + (size_t)r0 * ldc + col) =
                        packh2(acc[mi][nj][0] + b0, acc[mi][nj][1] + b1);
                if (r1 < M)
                    *reinterpret_cast<uint32_t*>(C + (size_t)r1 * ldc + col) =
                        packh2(acc[mi][nj][2] + b0, acc[mi][nj][3] + b1);
            } else {
                float* C = (float*)Cb;
                if (r0 < M) {
                    float2 v0 = make_float2(acc[mi][nj][0] + b0, acc[mi][nj][1] + b1);
                    *reinterpret_cast<float2*>(C + (size_t)r0 * ldc + col) = v0;
                }
                if (r1 < M) {
                    float2 v1 = make_float2(acc[mi][nj][2] + b0, acc[mi][nj][3] + b1);
                    *reinterpret_cast<float2*>(C + (size_t)r1 * ldc + col) = v1;
                }
            }
        }
    }
}

// ---------------------------------------------------------------------------
// Fused mega-launch: value (1662 CTAs, BM=128) + qproj (339 CTAs, BM=64).
// ---------------------------------------------------------------------------
__global__ __launch_bounds__(256, 2) void gemm_fused(
    const float* __restrict__ value, const float* __restrict__ query,
    const __half* __restrict__ wt,
    const float* __restrict__ b_val, const float* __restrict__ b_off,
    const float* __restrict__ b_attn,
    __half* __restrict__ vh, float* __restrict__ qp)
{
    extern __shared__ uint32_t sm[];
    const int bid = blockIdx.x;

    if (bid < NVB) {
        const int ty = bid >> 1, tx = bid & 1;
        gemm_tile<4, true>(value, MV, ty * 128,
                           wt + WT_VAL + (size_t)tx * 128 * 256, b_val + tx * 128,
                           vh + tx * 128, 256, sm);
    } else {
        const int q = bid - NVB;
        const int ty = q / 3, tx = q % 3;
        const __half* Bp = (tx < 2) ? (wt + WT_OFF + (size_t)tx * 128 * 256)
                                    : (wt + WT_ATTN);
        const float*  bb = (tx < 2) ? (b_off + tx * 128) : b_attn;
        gemm_tile<2, false>(query, BQ, ty * 64,
                            Bp, bb,
                            qp + tx * 128, 384, sm);
    }
}

// ---------------------------------------------------------------------------
// Output projection: single-stage full-K (round-15 validated). BM=64 x BN=128.
// ---------------------------------------------------------------------------
__global__ __launch_bounds__(256, 2) void gemm_out(
    const __half* __restrict__ A,      // tmp fp16 [BQ][256]
    const __half* __restrict__ wt, const float* __restrict__ bias,
    float* __restrict__ C)
{
    constexpr int RSTB = 528;              // bytes per smem row
    constexpr int ASZB = 64 * RSTB;        // 33792 B

    extern __shared__ uint32_t sm[];
    const int tid  = threadIdx.x;
    const int lane = tid & 31;
    const int w    = tid >> 5;
    const int gid  = lane >> 2;
    const int tig  = lane & 3;
    const int brow = blockIdx.y * 64;
    const int txb  = blockIdx.x;
    const __half* Bt = wt + WT_OUT + (size_t)txb * 128 * 256;
    const int m0 = (w >> 2) * 32;
    const int n0 = (w & 3) * 32;

    const uint32_t smbase = smem_u32(sm);

    #pragma unroll
    for (int i = 0; i < 8; i++) {
        int g = tid + i * 256, row = g >> 5, ch = g & 31;
        int gr = min(brow + row, BQ - 1);
        cp_async16(smbase + (uint32_t)row * RSTB + ch * 16,
                   A + (size_t)gr * 256 + ch * 8);
    }
    #pragma unroll
    for (int i = 0; i < 16; i++) {
        int g = tid + i * 256, n = g >> 5, ch = g & 31;
        cp_async16(smbase + ASZB + (uint32_t)n * RSTB + ch * 16,
                   Bt + (size_t)n * 256 + ch * 8);
    }
    CP_COMMIT();
    CP_WAIT0();
    __syncthreads();

    const uint32_t aAddr = smbase + (uint32_t)(m0 + (lane & 15)) * RSTB
                                  + ((lane & 16) ? 16u : 0u);
    const uint32_t bAddr = smbase + ASZB
                                  + (uint32_t)(n0 + (lane & 7) + ((lane & 16) ? 8 : 0)) * RSTB
                                  + ((lane & 8) ? 16u : 0u);

    float acc[2][4][4];
    #pragma unroll
    for (int mi = 0; mi < 2; mi++)
        #pragma unroll
        for (int nj = 0; nj < 4; nj++)
            #pragma unroll
            for (int r = 0; r < 4; r++) acc[mi][nj][r] = 0.f;

    #pragma unroll
    for (int kk = 0; kk < 16; kk++) {
        uint32_t a[2][4], b[4][2];
        #pragma unroll
        for (int mi = 0; mi < 2; mi++)
            ldsm_x4(a[mi][0], a[mi][1], a[mi][2], a[mi][3],
                    aAddr + mi * 16 * RSTB + kk * 32);
        #pragma unroll
        for (int njp = 0; njp < 2; njp++)
            ldsm_x4(b[2 * njp][0], b[2 * njp][1], b[2 * njp + 1][0], b[2 * njp + 1][1],
                    bAddr + njp * 16 * RSTB + kk * 32);
        #pragma unroll
        for (int mi = 0; mi < 2; mi++)
            #pragma unroll
            for (int nj = 0; nj < 4; nj++)
                HMMA16816(acc[mi][nj], a[mi], b[nj]);
    }

    #pragma unroll
    for (int mi = 0; mi < 2; mi++) {
        #pragma unroll
        for (int nj = 0; nj < 4; nj++) {
            int col = txb * 128 + n0 + nj * 8 + 2 * tig;
            float b0 = bias[col], b1 = bias[col + 1];
            int r0 = brow + m0 + mi * 16 + gid;
            int r1 = r0 + 8;
            if (r0 < BQ) {
                float2 v0 = make_float2(acc[mi][nj][0] + b0, acc[mi][nj][1] + b1);
                *reinterpret_cast<float2*>(C + (size_t)r0 * 256 + col) = v0;
            }
            if (r1 < BQ) {
                float2 v1 = make_float2(acc[mi][nj][2] + b0, acc[mi][nj][3] + b1);
                *reinterpret_cast<float2*>(C + (size_t)r1 * 256 + col) = v1;
            }
        }
    }
}

// ---------------------------------------------------------------------------
// Fused softmax + sampling over fp16 value; writes tmp as fp16.
// ---------------------------------------------------------------------------
__global__ __launch_bounds__(256) void msda_sample(
    const float* __restrict__ ref, const float* __restrict__ qp,
    const int* __restrict__ shapes, const int* __restrict__ starts,
    const __half* __restrict__ v, __half* __restrict__ tmp)
{
    const int bq  = blockIdx.x;
    const int b   = bq / Qn;
    const int tid = threadIdx.x;

    __shared__ int4   sIdx[128];
    __shared__ float4 sW[128];

    if (tid < 128) {
        const int l = (tid >> 2) & 3;
        const int Hl = shapes[2 * l], Wl = shapes[2 * l + 1];
        const int st = starts[l];

        float logit = qp[(size_t)bq * 384 + 256 + tid];
        float m = logit;
        #pragma unroll
        for (int d = 8; d >= 1; d >>= 1)
            m = fmaxf(m, __shfl_xor_sync(0xffffffffu, m, d));
        float e = __expf(logit - m);
        float s = e;
        #pragma unroll
        for (int d = 8; d >= 1; d >>= 1)
            s += __shfl_xor_sync(0xffffffffu, s, d);
        const float wgt = e / s;

        const float2 off = reinterpret_cast<const float2*>(qp + (size_t)bq * 384)[tid];
        const float rx = ref[(size_t)bq * (LEVELS * 2) + 2 * l];
        const float ry = ref[(size_t)bq * (LEVELS * 2) + 2 * l + 1];
        const float x = rx * (float)Wl + off.x - 0.5f;
        const float y = ry * (float)Hl + off.y - 0.5f;

        const float x0f = floorf(x), y0f = floorf(y);
        const int x0 = (int)x0f, y0 = (int)y0f;
        const float fx = x - x0f, fy = y - y0f;
        const int x1 = x0 + 1, y1 = y0 + 1;
        const bool bx0 = (x0 >= 0) & (x0 < Wl);
        const bool bx1 = (x1 >= 0) & (x1 < Wl);
        const bool by0 = (y0 >= 0) & (y0 < Hl);
        const bool by1 = (y1 >= 0) & (y1 < Hl);
        const int cx0 = min(max(x0, 0), Wl - 1), cx1 = min(max(x1, 0), Wl - 1);
        const int cy0 = min(max(y0, 0), Hl - 1), cy1 = min(max(y1, 0), Hl - 1);

        sIdx[tid] = make_int4(st + cy0 * Wl + cx0, st + cy0 * Wl + cx1,
                              st + cy1 * Wl + cx0, st + cy1 * Wl + cx1);
        sW[tid] = make_float4(
            (bx0 && by0) ? (1.f - fx) * (1.f - fy) * wgt : 0.f,
            (bx1 && by0) ? fx * (1.f - fy) * wgt : 0.f,
            (bx0 && by1) ? (1.f - fx) * fy * wgt : 0.f,
            (bx1 && by1) ? fx * fy * wgt : 0.f);
    }
    __syncthreads();

    const int h    = tid >> 5;
    const int lane = tid & 31;
    const int sgrp = lane >> 3;
    const int c8   = lane & 7;
    const __half* vb = v + (size_t)b * NUM_KEYS * EMBED + h * HEAD_DIM + 4 * c8;

    float a0 = 0.f, a1 = 0.f, a2 = 0.f, a3 = 0.f;
    #pragma unroll
    for (int j = 0; j < 4; j++) {
        const int s = h * 16 + sgrp * 4 + j;
        const int4   id = sIdx[s];
        const float4 wv = sW[s];
        uint2 r0 = *reinterpret_cast<const uint2*>(vb + (size_t)id.x * EMBED);
        uint2 r1 = *reinterpret_cast<const uint2*>(vb + (size_t)id.y * EMBED);
        uint2 r2 = *reinterpret_cast<const uint2*>(vb + (size_t)id.z * EMBED);
        uint2 r3 = *reinterpret_cast<const uint2*>(vb + (size_t)id.w * EMBED);
        float2 g0a = __half22float2(*reinterpret_cast<__half2*>(&r0.x));
        float2 g0b = __half22float2(*reinterpret_cast<__half2*>(&r0.y));
        float2 g1a = __half22float2(*reinterpret_cast<__half2*>(&r1.x));
        float2 g1b = __half22float2(*reinterpret_cast<__half2*>(&r1.y));
        float2 g2a = __half22float2(*reinterpret_cast<__half2*>(&r2.x));
        float2 g2b = __half22float2(*reinterpret_cast<__half2*>(&r2.y));
        float2 g3a = __half22float2(*reinterpret_cast<__half2*>(&r3.x));
        float2 g3b = __half22float2(*reinterpret_cast<__half2*>(&r3.y));
        a0 = fmaf(wv.x, g0a.x, a0); a1 = fmaf(wv.x, g0a.y, a1);
        a2 = fmaf(wv.x, g0b.x, a2); a3 = fmaf(wv.x, g0b.y, a3);
        a0 = fmaf(wv.y, g1a.x, a0); a1 = fmaf(wv.y, g1a.y, a1);
        a2 = fmaf(wv.y, g1b.x, a2); a3 = fmaf(wv.y, g1b.y, a3);
        a0 = fmaf(wv.z, g2a.x, a0); a1 = fmaf(wv.z, g2a.y, a1);
        a2 = fmaf(wv.z, g2b.x, a2); a3 = fmaf(wv.z, g2b.y, a3);
        a0 = fmaf(wv.w, g3a.x, a0); a1 = fmaf(wv.w, g3a.y, a1);
        a2 = fmaf(wv.w, g3b.x, a2); a3 = fmaf(wv.w, g3b.y, a3);
    }
    #pragma unroll
    for (int d = 8; d <= 16; d <<= 1) {
        a0 += __shfl_xor_sync(0xffffffffu, a0, d);
        a1 += __shfl_xor_sync(0xffffffffu, a1, d);
        a2 += __shfl_xor_sync(0xffffffffu, a2, d);
        a3 += __shfl_xor_sync(0xffffffffu, a3, d);
    }
    if (sgrp == 0) {
        uint2 o = { packh2(a0, a1), packh2(a2, a3) };
        *reinterpret_cast<uint2*>(tmp + (size_t)bq * 256 + h * HEAD_DIM + 4 * c8) = o;
    }
}

// ---------------------------------------------------------------------------
extern "C" void kernel_launch(void* const* d_in, const int* in_sizes, int n_in,
                              void* d_out, int out_size)
{
    const float* query  = (const float*)d_in[0];
    const float* refpts = (const float*)d_in[1];
    const float* value  = (const float*)d_in[2];
    const int*   shapes = (const int*)  d_in[3];
    const int*   starts = (const int*)  d_in[4];
    const float* W_off  = (const float*)d_in[5];
    const float* b_off  = (const float*)d_in[6];
    const float* W_attn = (const float*)d_in[7];
    const float* b_attn = (const float*)d_in[8];
    const float* W_val  = (const float*)d_in[9];
    const float* b_val  = (const float*)d_in[10];
    const float* W_out  = (const float*)d_in[11];
    const float* b_out  = (const float*)d_in[12];
    float* out = (float*)d_out;

    __half *pvh, *pwt, *ptmph;
    float *pqp;
    cudaGetSymbolAddress((void**)&pvh,   g_vh);
    cudaGetSymbolAddress((void**)&pqp,   g_qp);
    cudaGetSymbolAddress((void**)&ptmph, g_tmph);
    cudaGetSymbolAddress((void**)&pwt,   g_wt);

    const int SMEMF = (2 * 128 * 20 + 3 * 128 * 20) * 4;   // 51200 B (A x2 + B x3)
    const int SMEMO = (64 + 128) * 528;                    // 101376 B
    cudaFuncSetAttribute(gemm_fused, cudaFuncAttributeMaxDynamicSharedMemorySize, SMEMF);
    cudaFuncSetAttribute(gemm_out,   cudaFuncAttributeMaxDynamicSharedMemorySize, SMEMO);

    // 0) transpose+convert all weights to fp16 [n][k]
    transpose_w<<<dim3(8, 8, 4), dim3(32, 8)>>>(W_val, W_off, W_attn, W_out, pwt);
    // 1) value projection (fp16 out) + combined query projection, one launch
    gemm_fused<<<NVB + NQB, 256, SMEMF>>>(value, query, pwt,
                                          b_val, b_off, b_attn, pvh, pqp);
    // 2) fused softmax + sampling -> fp16 tmp
    msda_sample<<<BQ, 256>>>(refpts, pqp, shapes, starts, pvh, ptmph);
    // 3) output projection: single-stage, [7200,256] @ [256,256]
    {
        dim3 grid(2, NQB_Y);
        gemm_out<<<grid, 256, SMEMO>>>(ptmph, pwt, b_out, out);
    }
}